// round 2
// baseline (speedup 1.0000x reference)
#include <cuda_runtime.h>
#include <cstdint>

#define BB    32
#define DIMS  8
#define DEG   32
#define P     4
#define TPB   256

__device__ __forceinline__ float ex2f(float x) {
    float r;
    asm("ex2.approx.f32 %0, %1;" : "=f"(r) : "f"(x));
    return r;
}
__device__ __forceinline__ uint64_t pack2(float lo, float hi) {
    uint64_t r;
    asm("mov.b64 %0, {%1, %2};" : "=l"(r) : "f"(lo), "f"(hi));
    return r;
}
__device__ __forceinline__ void unpack2(uint64_t v, float& lo, float& hi) {
    asm("mov.b64 {%0, %1}, %2;" : "=f"(lo), "=f"(hi) : "l"(v));
}
__device__ __forceinline__ uint64_t fma2(uint64_t a, uint64_t b, uint64_t c) {
    uint64_t r;
    asm("fma.rn.f32x2 %0, %1, %2, %3;" : "=l"(r) : "l"(a), "l"(b), "l"(c));
    return r;
}
__device__ __forceinline__ uint64_t mul2(uint64_t a, uint64_t b) {
    uint64_t r;
    asm("mul.rn.f32x2 %0, %1, %2;" : "=l"(r) : "l"(a), "l"(b));
    return r;
}

__global__ __launch_bounds__(TPB, 4) void basis_kernel(
    const float* __restrict__ weights,    // (B, DIMS, DEG)
    const float* __restrict__ positions,  // (B, N)
    float* __restrict__ out,              // (B, N, DIMS) [+ zeros half]
    int N, int write_zeros)
{
    // weights duplicated into pairs, layout [g][d] -> (w, w)
    __shared__ uint64_t sw2[DEG * DIMS];

    const int b   = blockIdx.y;
    const int tid = threadIdx.x;

    {
        const int g = tid >> 3;      // tid = g*8 + d
        const int d = tid & 7;
        const float w = weights[b * DIMS * DEG + d * DEG + g];
        sw2[tid] = pack2(w, w);
    }
    __syncthreads();

    const int n0 = blockIdx.x * (TPB * P) + tid * P;

    const float4 xv = *reinterpret_cast<const float4*>(positions + (size_t)b * N + n0);
    float x[P] = {xv.x, xv.y, xv.z, xv.w};

    // centers c_g = g*s, s = 1.01/31.  exp(-(x-c)^2 * 12.5) in base 2:
    //   e_0 = 2^(-L x^2),  t_0 = e_1/e_0 = 2^(L s (2x - s)),  t_{g+1} = t_g * u,
    //   u = 2^(-2 L s^2)   (L = 12.5 * log2(e))
    const float s = 1.01f / 31.0f;
    const float L = 12.5f * 1.4426950408889634f;

    const float u = ex2f(-2.0f * L * s * s);
    const uint64_t u2 = pack2(u, u);

    float e0[P], t0[P];
#pragma unroll
    for (int p = 0; p < P; p++) {
        e0[p] = ex2f(-L * x[p] * x[p]);
        t0[p] = ex2f(L * s * (2.0f * x[p] - s));
    }
    uint64_t eA = pack2(e0[0], e0[1]), eB = pack2(e0[2], e0[3]);
    uint64_t tA = pack2(t0[0], t0[1]), tB = pack2(t0[2], t0[3]);

    uint64_t accA[DIMS], accB[DIMS];
#pragma unroll
    for (int d = 0; d < DIMS; d++) { accA[d] = 0ull; accB[d] = 0ull; }

#pragma unroll
    for (int g = 0; g < DEG; g++) {
        const uint64_t* wrow = sw2 + g * DIMS;
#pragma unroll
        for (int d = 0; d < DIMS; d++) {
            const uint64_t w2 = wrow[d];              // one LDS.64 feeds both positions
            accA[d] = fma2(eA, w2, accA[d]);
            accB[d] = fma2(eB, w2, accB[d]);
        }
        eA = mul2(eA, tA); tA = mul2(tA, u2);
        eB = mul2(eB, tB); tB = mul2(tB, u2);
    }

    // Unpack: accA[d] = (pos0.d, pos1.d), accB[d] = (pos2.d, pos3.d)
    float r[P][DIMS];
#pragma unroll
    for (int d = 0; d < DIMS; d++) {
        unpack2(accA[d], r[0][d], r[1][d]);
        unpack2(accB[d], r[2][d], r[3][d]);
    }

    const size_t base = ((size_t)b * N + n0) * DIMS;
#pragma unroll
    for (int p = 0; p < P; p++) {
        float4 v0 = {r[p][0], r[p][1], r[p][2], r[p][3]};
        float4 v1 = {r[p][4], r[p][5], r[p][6], r[p][7]};
        *reinterpret_cast<float4*>(out + base + (size_t)p * DIMS)     = v0;
        *reinterpret_cast<float4*>(out + base + (size_t)p * DIMS + 4) = v1;
    }

    if (write_zeros) {
        const size_t R = (size_t)gridDim.y * (size_t)N * DIMS;
        const float4 z = {0.0f, 0.0f, 0.0f, 0.0f};
#pragma unroll
        for (int p = 0; p < P; p++) {
            *reinterpret_cast<float4*>(out + R + base + (size_t)p * DIMS)     = z;
            *reinterpret_cast<float4*>(out + R + base + (size_t)p * DIMS + 4) = z;
        }
    }
}

extern "C" void kernel_launch(void* const* d_in, const int* in_sizes, int n_in,
                              void* d_out, int out_size)
{
    const float* weights   = (const float*)d_in[0];
    const float* positions = (const float*)d_in[2];
    float* out = (float*)d_out;

    const int N = in_sizes[2] / BB;                 // 65536
    const long long R = (long long)BB * N * DIMS;
    const int write_zeros = (out_size >= 2 * R) ? 1 : 0;

    dim3 grid(N / (TPB * P), BB);                   // (64, 32)
    basis_kernel<<<grid, TPB>>>(weights, positions, out, N, write_zeros);
}

// round 3
// speedup vs baseline: 1.0881x; 1.0881x over previous
#include <cuda_runtime.h>
#include <cstdint>

#define BB    32
#define DIMS  8
#define DEG   32
#define P     4
#define TPB   256

__device__ __forceinline__ float ex2f(float x) {
    float r;
    asm("ex2.approx.f32 %0, %1;" : "=f"(r) : "f"(x));
    return r;
}
__device__ __forceinline__ unsigned long long pack2(float lo, float hi) {
    unsigned long long r;
    asm("mov.b64 %0, {%1, %2};" : "=l"(r) : "f"(lo), "f"(hi));
    return r;
}
__device__ __forceinline__ unsigned long long fma2(unsigned long long a,
                                                   unsigned long long b,
                                                   unsigned long long c) {
    unsigned long long r;
    asm("fma.rn.f32x2 %0, %1, %2, %3;" : "=l"(r) : "l"(a), "l"(b), "l"(c));
    return r;
}
__device__ __forceinline__ unsigned long long mul2(unsigned long long a,
                                                   unsigned long long b) {
    unsigned long long r;
    asm("mul.rn.f32x2 %0, %1, %2;" : "=l"(r) : "l"(a), "l"(b));
    return r;
}

__global__ __launch_bounds__(TPB) void basis_kernel(
    const float* __restrict__ weights,    // (B, DIMS, DEG)
    const float* __restrict__ positions,  // (B, N)
    float* __restrict__ out,              // (B, N, DIMS) [+ zeros half]
    int N, int write_zeros)
{
    // sw2[g*4 + dp] = (w[2dp][g], w[2dp+1][g])  — dim-pair packed, per center g
    __shared__ __align__(16) unsigned long long sw2[DEG * 4];

    const int b   = blockIdx.y;
    const int tid = threadIdx.x;

    {
        // float view index = g*8 + d == tid  (g = tid>>3, d = tid&7)
        const int g = tid >> 3;
        const int d = tid & 7;
        reinterpret_cast<float*>(sw2)[tid] = weights[b * DIMS * DEG + d * DEG + g];
    }
    __syncthreads();

    const int n0 = blockIdx.x * (TPB * P) + tid * P;

    const float4 xv = *reinterpret_cast<const float4*>(positions + (size_t)b * N + n0);
    float x[P] = {xv.x, xv.y, xv.z, xv.w};

    // centers c_g = g*s, s = 1.01/31.  exp(-12.5*(x-c)^2) in base 2:
    //   e_0 = 2^(-L x^2),  t_0 = 2^(L s (2x - s)),  e_{g+1}=e_g*t_g, t_{g+1}=t_g*u,
    //   u = 2^(-2 L s^2),  L = 12.5*log2(e)
    const float s = 1.01f / 31.0f;
    const float L = 12.5f * 1.4426950408889634f;
    const float u = ex2f(-2.0f * L * s * s);
    const unsigned long long u2 = pack2(u, u);

    // Duplicated-pair recurrence state: (e_p, e_p), (t_p, t_p) — duplication
    // is invariant under the recurrence, so it's paid only once here.
    unsigned long long eD[P], tD[P];
#pragma unroll
    for (int p = 0; p < P; p++) {
        const float e0 = ex2f(-L * x[p] * x[p]);
        const float t0 = ex2f(L * s * (2.0f * x[p] - s));
        eD[p] = pack2(e0, e0);
        tD[p] = pack2(t0, t0);
    }

    // acc[p][dp] = (result[p][2dp], result[p][2dp+1])
    unsigned long long acc[P][4];
#pragma unroll
    for (int p = 0; p < P; p++)
#pragma unroll
        for (int dp = 0; dp < 4; dp++)
            acc[p][dp] = 0ull;

#pragma unroll
    for (int g = 0; g < DEG; g++) {
        // 2 LDS.128 broadcasts fetch all 8 weights for this center
        const ulonglong2 w01 = *reinterpret_cast<const ulonglong2*>(sw2 + g * 4);
        const ulonglong2 w23 = *reinterpret_cast<const ulonglong2*>(sw2 + g * 4 + 2);
#pragma unroll
        for (int p = 0; p < P; p++) {
            acc[p][0] = fma2(eD[p], w01.x, acc[p][0]);
            acc[p][1] = fma2(eD[p], w01.y, acc[p][1]);
            acc[p][2] = fma2(eD[p], w23.x, acc[p][2]);
            acc[p][3] = fma2(eD[p], w23.y, acc[p][3]);
            eD[p] = mul2(eD[p], tD[p]);
            tD[p] = mul2(tD[p], u2);
        }
    }

    const size_t base = ((size_t)b * N + n0) * DIMS;
#pragma unroll
    for (int p = 0; p < P; p++) {
        ulonglong2 v0; v0.x = acc[p][0]; v0.y = acc[p][1];
        ulonglong2 v1; v1.x = acc[p][2]; v1.y = acc[p][3];
        *reinterpret_cast<ulonglong2*>(out + base + (size_t)p * DIMS)     = v0;
        *reinterpret_cast<ulonglong2*>(out + base + (size_t)p * DIMS + 4) = v1;
    }

    if (write_zeros) {
        const size_t R = (size_t)gridDim.y * (size_t)N * DIMS;
        const float4 z = {0.0f, 0.0f, 0.0f, 0.0f};
#pragma unroll
        for (int p = 0; p < P; p++) {
            *reinterpret_cast<float4*>(out + R + base + (size_t)p * DIMS)     = z;
            *reinterpret_cast<float4*>(out + R + base + (size_t)p * DIMS + 4) = z;
        }
    }
}

extern "C" void kernel_launch(void* const* d_in, const int* in_sizes, int n_in,
                              void* d_out, int out_size)
{
    const float* weights   = (const float*)d_in[0];
    const float* positions = (const float*)d_in[2];
    float* out = (float*)d_out;

    const int N = in_sizes[2] / BB;                 // 65536
    const long long R = (long long)BB * N * DIMS;
    const int write_zeros = (out_size >= 2 * R) ? 1 : 0;

    dim3 grid(N / (TPB * P), BB);                   // (64, 32)
    basis_kernel<<<grid, TPB>>>(weights, positions, out, N, write_zeros);
}